// round 16
// baseline (speedup 1.0000x reference)
#include <cuda_runtime.h>
#include <cuda_bf16.h>
#include <cuda_fp8.h>
#include <math.h>

#define B_   8
#define S_   1024
#define H_   12
#define D_   64
#define HID  768
#define KTOP 6
#define NROWS (B_ * S_)        // 8192
#define NZ    (B_ * H_)        // 96
#define NW   (HID * HID)       // 589824

typedef unsigned int u32;
typedef unsigned char u8;
typedef __nv_bfloat16 bf16;

// ---------------- scratch ----------------
__device__ float g_rpart[B_ * 32 * HID];
__device__ float g_mask[NZ];
__device__ u8    g_x8[NROWS * HID];                // X in fp8 e4m3
__device__ u8    g_w8[3][NW];                      // Wq^T,Wk^T,Wv^T fp8 [n][k], scaled x16
__device__ bf16  g_wo[NW];                         // Wo bf16 [k][n]
__device__ bf16  g_q[NZ * S_ * D_];                // Q pre-scaled by 0.125
__device__ bf16  g_k[NZ * S_ * D_];
__device__ bf16  g_v[NZ * S_ * D_];
__device__ bf16  g_xc[NROWS * HID];                // flat ctx bf16 (masked head cols never read)
__device__ float g_x[NROWS * HID];                 // pre-LN activations fp32

// ---------------- asm helpers ----------------
__device__ __forceinline__ u32 sptr(const void* p) {
    return (u32)__cvta_generic_to_shared(p);
}
#define CP16(d, s) asm volatile("cp.async.cg.shared.global [%0],[%1],16;\n" :: "r"(d), "l"(s))
#define CPCOMMIT() asm volatile("cp.async.commit_group;\n")
#define CPWAIT0()  asm volatile("cp.async.wait_group 0;\n")
#define CPWAIT1()  asm volatile("cp.async.wait_group 1;\n")
#define CPWAIT2()  asm volatile("cp.async.wait_group 2;\n")

__device__ __forceinline__ void ldsm4(u32 (&r)[4], u32 a) {
    asm volatile("ldmatrix.sync.aligned.m8n8.x4.shared.b16 {%0,%1,%2,%3},[%4];"
                 : "=r"(r[0]), "=r"(r[1]), "=r"(r[2]), "=r"(r[3]) : "r"(a));
}
__device__ __forceinline__ void ldsm4t(u32 (&r)[4], u32 a) {
    asm volatile("ldmatrix.sync.aligned.m8n8.x4.trans.shared.b16 {%0,%1,%2,%3},[%4];"
                 : "=r"(r[0]), "=r"(r[1]), "=r"(r[2]), "=r"(r[3]) : "r"(a));
}
__device__ __forceinline__ void mma16816(float (&d)[4], const u32 (&a)[4], u32 b0, u32 b1) {
    asm volatile(
        "mma.sync.aligned.m16n8k16.row.col.f32.bf16.bf16.f32 "
        "{%0,%1,%2,%3},{%4,%5,%6,%7},{%8,%9},{%0,%1,%2,%3};"
        : "+f"(d[0]), "+f"(d[1]), "+f"(d[2]), "+f"(d[3])
        : "r"(a[0]), "r"(a[1]), "r"(a[2]), "r"(a[3]), "r"(b0), "r"(b1));
}
__device__ __forceinline__ void mma16832f8(float (&d)[4], const u32 (&a)[4], u32 b0, u32 b1) {
    asm volatile(
        "mma.sync.aligned.m16n8k32.row.col.f32.e4m3.e4m3.f32 "
        "{%0,%1,%2,%3},{%4,%5,%6,%7},{%8,%9},{%0,%1,%2,%3};"
        : "+f"(d[0]), "+f"(d[1]), "+f"(d[2]), "+f"(d[3])
        : "r"(a[0]), "r"(a[1]), "r"(a[2]), "r"(a[3]), "r"(b0), "r"(b1));
}
__device__ __forceinline__ u32 pkbf(float x, float y) {
    __nv_bfloat162 t = __floats2bfloat162_rn(x, y);
    return *(u32*)&t;
}
__device__ __forceinline__ u8 f2e4m3(float v) {
    return (u8)__nv_cvt_float_to_fp8(v, __NV_SATFINITE, __NV_E4M3);
}

// ---------------- prep: weight cvt (z<4) + X mean/fp8 cvt (z==4), one launch ----------------
__global__ void prep_kernel(const float* __restrict__ X,
                            const float* __restrict__ a, const float* __restrict__ b,
                            const float* __restrict__ c, const float* __restrict__ d) {
    int z = blockIdx.z;
    if (z < 4) {
        if (blockIdx.y >= 24) return;
        const float* s = (z == 0) ? a : (z == 1) ? b : (z == 2) ? c : d;
        __shared__ float t[32][33];
        int k0 = blockIdx.x * 32, nn0 = blockIdx.y * 32;
        int tr = threadIdx.x >> 5, tc = threadIdx.x & 31;
        #pragma unroll
        for (int p = 0; p < 4; p++)
            t[p * 8 + tr][tc] = s[(size_t)(k0 + p * 8 + tr) * HID + nn0 + tc];
        __syncthreads();
        if (z < 3) {
            #pragma unroll
            for (int p = 0; p < 4; p++)
                g_w8[z][(size_t)(nn0 + p * 8 + tr) * HID + k0 + tc] = f2e4m3(t[tc][p * 8 + tr] * 16.0f);
        } else {
            #pragma unroll
            for (int p = 0; p < 4; p++)
                g_wo[(size_t)(k0 + p * 8 + tr) * HID + nn0 + tc] = __float2bfloat16(t[p * 8 + tr][tc]);
        }
    } else {
        if (blockIdx.x >= 8) return;
        int bb = blockIdx.x, chunk = blockIdx.y, tid = threadIdx.x;
        size_t row0 = (size_t)bb * S_ + chunk * 32;
        const float* Xb = X + row0 * HID;
        u8* Ob = g_x8 + row0 * HID;
        #pragma unroll
        for (int j = 0; j < 3; j++) {
            int cc = tid + j * 256;
            float s = 0.f;
            #pragma unroll 8
            for (int r = 0; r < 32; r++) {
                float v = Xb[r * HID + cc];
                s += v;
                Ob[r * HID + cc] = f2e4m3(v);
            }
            g_rpart[(bb * 32 + chunk) * HID + cc] = s;
        }
    }
}

__global__ void router_kernel(const float* __restrict__ Wr, const float* __restrict__ br) {
    __shared__ float rin[HID];
    __shared__ float logits[H_];
    int b = blockIdx.x, tid = threadIdx.x;
    #pragma unroll
    for (int j = 0; j < 3; j++) {
        int c = tid + j * 256;
        float s = 0.f;
        #pragma unroll
        for (int p = 0; p < 32; p++) s += g_rpart[(b * 32 + p) * HID + c];
        rin[c] = s * (1.0f / S_);
    }
    __syncthreads();
    int warp = tid >> 5, lane = tid & 31;
    for (int h = warp; h < H_; h += 8) {
        float s = 0.f;
        for (int c = lane; c < HID; c += 32) s += rin[c] * Wr[c * H_ + h];
        #pragma unroll
        for (int o = 16; o > 0; o >>= 1) s += __shfl_xor_sync(0xffffffffu, s, o);
        if (lane == 0) logits[h] = s + br[h];
    }
    __syncthreads();
    if (tid < H_) {
        float v = logits[tid];
        int rank = 0;
        #pragma unroll
        for (int j = 0; j < H_; j++) {
            float u = logits[j];
            if (u > v || (u == v && j < tid)) rank++;
        }
        g_mask[b * H_ + tid] = (rank < KTOP) ? 1.0f : 0.0f;
    }
}

// ============ QKV fp8: merged q/k/v, 4-stage pipeline, m16n8k32 e4m3 ============
#define Q8_A_ST  10240
#define Q8_B_ST  5120
#define Q8_B_OFF (4 * Q8_A_ST)
#define Q8_SMEM  (Q8_B_OFF + 4 * 3 * Q8_B_ST)   // 102400 bytes

__global__ void __launch_bounds__(256, 1) qkv_gemm(
    const float* __restrict__ bq, const float* __restrict__ bk, const float* __restrict__ bv) {
    int head = blockIdx.x;
    int m0 = blockIdx.y * 128;
    int bb = m0 >> 10;
    if (g_mask[bb * H_ + head] == 0.f) return;

    extern __shared__ u8 qsm[];
    u32 smem_u = sptr(qsm);
    int n0 = head * D_;

    int tid = threadIdx.x, lane = tid & 31, wid = tid >> 5;
    int wm = (wid >> 1) * 32, wn = (wid & 1) * 32;
    float acc[3][2][4][4] = {};

    int arow = tid >> 1, ahalf = (tid & 1) * 32;
    int brow = tid >> 2, bq16 = (tid & 3) * 16;
    const u8* Abase = g_x8 + (size_t)(m0 + arow) * HID + ahalf;

    #define Q8_LOAD(KT, BUF)                                                        \
        {                                                                           \
            const u8* Ag = Abase + (KT) * 64;                                       \
            u32 ad = smem_u + (BUF) * Q8_A_ST + arow * 80 + ahalf;                  \
            CP16(ad, Ag); CP16(ad + 16, Ag + 16);                                   \
            size_t woff = (size_t)(n0 + brow) * HID + (KT) * 64 + bq16;             \
            u32 bd = smem_u + Q8_B_OFF + (BUF) * 3 * Q8_B_ST + brow * 80 + bq16;    \
            CP16(bd, g_w8[0] + woff);                                               \
            CP16(bd + Q8_B_ST, g_w8[1] + woff);                                     \
            CP16(bd + 2 * Q8_B_ST, g_w8[2] + woff);                                 \
        }

    Q8_LOAD(0, 0) CPCOMMIT();
    Q8_LOAD(1, 1) CPCOMMIT();
    Q8_LOAD(2, 2) CPCOMMIT();

    int ar8 = (lane & 7) + ((lane >> 3) & 1) * 8;
    int ac8 = (lane >> 4) * 8;
    int br8 = (lane & 7) + (lane >> 4) * 8;
    int bc8 = ((lane >> 3) & 1) * 8;

    for (int c = 0; c < 12; c++) {
        int cur = c & 3;
        if (c < 10) CPWAIT2(); else if (c < 11) CPWAIT1(); else CPWAIT0();
        __syncthreads();
        if (c < 9) { Q8_LOAD(c + 3, (c + 3) & 3) CPCOMMIT(); }

        u32 Abuf = smem_u + cur * Q8_A_ST;
        u32 Bbuf = smem_u + Q8_B_OFF + cur * 3 * Q8_B_ST;
        #pragma unroll
        for (int kk = 0; kk < 2; kk++) {
            u32 a[2][4];
            #pragma unroll
            for (int mi = 0; mi < 2; mi++) {
                int r = wm + mi * 16 + ar8;
                ldsm4(a[mi], Abuf + r * 80 + (kk * 16 + ac8) * 2);
            }
            #pragma unroll
            for (int z = 0; z < 3; z++) {
                u32 bfr[2][4];
                #pragma unroll
                for (int nj = 0; nj < 2; nj++) {
                    int rn = wn + nj * 16 + br8;
                    ldsm4(bfr[nj], Bbuf + z * Q8_B_ST + rn * 80 + (kk * 16 + bc8) * 2);
                }
                #pragma unroll
                for (int mi = 0; mi < 2; mi++)
                    #pragma unroll
                    for (int jn = 0; jn < 4; jn++)
                        mma16832f8(acc[z][mi][jn], a[mi],
                                   bfr[jn >> 1][(jn & 1) * 2], bfr[jn >> 1][(jn & 1) * 2 + 1]);
            }
        }
    }

    #pragma unroll
    for (int z = 0; z < 3; z++) {
        const float* bias = (z == 0) ? bq : (z == 1) ? bk : bv;
        bf16* out = (z == 0) ? g_q : (z == 1) ? g_k : g_v;
        float qscale = (z == 0) ? 0.125f : 1.0f;
        #pragma unroll
        for (int mi = 0; mi < 2; mi++) {
            int r0 = m0 + wm + mi * 16 + (lane >> 2);
            int s0 = r0 & (S_ - 1);
            #pragma unroll
            for (int jn = 0; jn < 4; jn++) {
                int co = wn + jn * 8 + (lane & 3) * 2;
                float b0f = bias[n0 + co], b1f = bias[n0 + co + 1];
                float c0 = (acc[z][mi][jn][0] * 0.0625f + b0f) * qscale;
                float c1 = (acc[z][mi][jn][1] * 0.0625f + b1f) * qscale;
                float c2 = (acc[z][mi][jn][2] * 0.0625f + b0f) * qscale;
                float c3 = (acc[z][mi][jn][3] * 0.0625f + b1f) * qscale;
                size_t base = ((size_t)(bb * H_ + head) * S_ + s0) * D_ + co;
                *(__nv_bfloat162*)&out[base] = __floats2bfloat162_rn(c0, c1);
                *(__nv_bfloat162*)&out[base + 8 * D_] = __floats2bfloat162_rn(c2, c3);
            }
        }
    }
}

// ============ Flash attention: BM=64, 128 threads, 2 CTAs/SM ============
// smem rows of [72] bf16: Q rows 0-63, K bufs at 64+cur*128, V at 320+cur*128
#define FLASH_SMEM (576 * 72 * 2)   // 82944 bytes

__global__ void __launch_bounds__(128, 2) flash_kernel() {
    extern __shared__ bf16 fsm[];
    bf16 (*SM)[72] = (bf16(*)[72])fsm;
    int z = blockIdx.y;
    if (g_mask[z] == 0.f) return;
    int m0 = blockIdx.x * 64;
    int bb = z / H_, h = z % H_;
    int tid = threadIdx.x, lane = tid & 31, wid = tid >> 5;   // wid 0..3

    const bf16* Qg = g_q + ((size_t)z << 16);
    const bf16* Kg = g_k + ((size_t)z << 16);
    const bf16* Vg = g_v + ((size_t)z << 16);

    // K/V tile loader: 128 rows, 1 thread per row, 8x CP16
    #define LD_KV128(DST, GP)                                         \
        {                                                             \
            u32 d = sptr(&SM[(DST) + tid][0]);                        \
            const bf16* s = (GP) + (size_t)tid * D_;                  \
            CP16(d, s);        CP16(d + 16, s + 8);                   \
            CP16(d + 32, s + 16); CP16(d + 48, s + 24);               \
            CP16(d + 64, s + 32); CP16(d + 80, s + 40);               \
            CP16(d + 96, s + 48); CP16(d + 112, s + 56);              \
        }
    // Q tile loader: 64 rows, 2 threads per row, 4x CP16
    {
        int arow = tid >> 1, acol = (tid & 1) << 5;
        u32 d = sptr(&SM[arow][acol]);
        const bf16* s = Qg + (size_t)(m0 + arow) * D_ + acol;
        CP16(d, s); CP16(d + 16, s + 8);
        CP16(d + 32, s + 16); CP16(d + 48, s + 24);
    }
    LD_KV128(64, Kg)
    LD_KV128(320, Vg)
    CPCOMMIT();
    LD_KV128(192, Kg + (size_t)128 * D_)
    LD_KV128(448, Vg + (size_t)128 * D_)
    CPCOMMIT();
    CPWAIT1();
    __syncthreads();

    // Q fragments (register-resident)
    u32 qa[4][4];
    {
        int qr = wid * 16 + (lane & 7) + ((lane >> 3) & 1) * 8;
        int qc = (lane >> 4) * 8;
        #pragma unroll
        for (int kc = 0; kc < 4; kc++)
            ldsm4(qa[kc], sptr(&SM[qr][kc * 16 + qc]));
    }

    float mrow0 = -1e30f, mrow1 = -1e30f;
    float lsum0 = 0.f, lsum1 = 0.f;
    float oacc[8][4] = {};

    for (int kt = 0; kt < 8; kt++) {
        int cur = kt & 1;
        int kbase = 64 + cur * 128;
        int vbase = 320 + cur * 128;

        float sacc[16][4] = {};
        {
            int rn8 = (lane & 7) + (lane >> 4) * 8;
            int ck8 = ((lane >> 3) & 1) * 8;
            #pragma unroll
            for (int nc = 0; nc < 8; nc++) {
                #pragma unroll
                for (int kc = 0; kc < 4; kc++) {
                    u32 kb[4];
                    ldsm4(kb, sptr(&SM[kbase + nc * 16 + rn8][kc * 16 + ck8]));
                    mma16816(sacc[nc * 2],     qa[kc], kb[0], kb[1]);
                    mma16816(sacc[nc * 2 + 1], qa[kc], kb[2], kb[3]);
                }
            }
        }

        float ml0 = mrow0, ml1 = mrow1;
        #pragma unroll
        for (int nj = 0; nj < 16; nj++) {
            ml0 = fmaxf(ml0, fmaxf(sacc[nj][0], sacc[nj][1]));
            ml1 = fmaxf(ml1, fmaxf(sacc[nj][2], sacc[nj][3]));
        }
        ml0 = fmaxf(ml0, __shfl_xor_sync(0xffffffffu, ml0, 1));
        ml0 = fmaxf(ml0, __shfl_xor_sync(0xffffffffu, ml0, 2));
        ml1 = fmaxf(ml1, __shfl_xor_sync(0xffffffffu, ml1, 1));
        ml1 = fmaxf(ml1, __shfl_xor_sync(0xffffffffu, ml1, 2));
        float al0 = __expf(mrow0 - ml0), al1 = __expf(mrow1 - ml1);
        mrow0 = ml0; mrow1 = ml1;
        lsum0 *= al0; lsum1 *= al1;

        u32 pb[16][2];
        #pragma unroll
        for (int nj = 0; nj < 16; nj++) {
            float p0 = __expf(sacc[nj][0] - ml0), p1 = __expf(sacc[nj][1] - ml0);
            float p2 = __expf(sacc[nj][2] - ml1), p3 = __expf(sacc[nj][3] - ml1);
            lsum0 += p0 + p1; lsum1 += p2 + p3;
            pb[nj][0] = pkbf(p0, p1);
            pb[nj][1] = pkbf(p2, p3);
        }
        #pragma unroll
        for (int nj = 0; nj < 8; nj++) {
            oacc[nj][0] *= al0; oacc[nj][1] *= al0;
            oacc[nj][2] *= al1; oacc[nj][3] *= al1;
        }

        {
            int vr8 = (lane & 7) + ((lane >> 3) & 1) * 8;
            int vc8 = (lane >> 4) * 8;
            #pragma unroll
            for (int pc = 0; pc < 8; pc++) {
                u32 pa[4] = {pb[pc * 2][0], pb[pc * 2][1], pb[pc * 2 + 1][0], pb[pc * 2 + 1][1]};
                #pragma unroll
                for (int vc = 0; vc < 4; vc++) {
                    u32 vb[4];
                    ldsm4t(vb, sptr(&SM[vbase + pc * 16 + vr8][vc * 16 + vc8]));
                    mma16816(oacc[vc * 2],     pa, vb[0], vb[1]);
                    mma16816(oacc[vc * 2 + 1], pa, vb[2], vb[3]);
                }
            }
        }

        __syncthreads();
        if (kt < 6) {
            int nb = kt + 2;
            LD_KV128(64 + cur * 128, Kg + (size_t)(nb * 128) * D_)
            LD_KV128(320 + cur * 128, Vg + (size_t)(nb * 128) * D_)
            CPCOMMIT();
            CPWAIT1();
            __syncthreads();
        } else if (kt == 6) {
            CPWAIT0();
            __syncthreads();
        }
    }

    lsum0 += __shfl_xor_sync(0xffffffffu, lsum0, 1);
    lsum0 += __shfl_xor_sync(0xffffffffu, lsum0, 2);
    lsum1 += __shfl_xor_sync(0xffffffffu, lsum1, 1);
    lsum1 += __shfl_xor_sync(0xffffffffu, lsum1, 2);
    float inv0 = 1.0f / lsum0, inv1 = 1.0f / lsum1;
    int r0 = m0 + wid * 16 + (lane >> 2);
    #pragma unroll
    for (int nj = 0; nj < 8; nj++) {
        int col = nj * 8 + (lane & 3) * 2;
        size_t b0 = (size_t)(bb * S_ + r0) * HID + h * D_ + col;
        *(__nv_bfloat162*)&g_xc[b0] = __floats2bfloat162_rn(oacc[nj][0] * inv0, oacc[nj][1] * inv0);
        *(__nv_bfloat162*)&g_xc[b0 + 8 * HID] = __floats2bfloat162_rn(oacc[nj][2] * inv1, oacc[nj][3] * inv1);
    }
}

// ============ x = ctx @ Wo + bo + residual; skip masked-head K-chunks ============
__global__ void __launch_bounds__(256, 2) out_gemm(
    const float* __restrict__ X, const float* __restrict__ bo) {
    __shared__ bf16 As[2][128][56];
    __shared__ bf16 Bs[2][32][136];
    int tid = threadIdx.x, lane = tid & 31, wid = tid >> 5;
    int wm = (wid >> 2) * 64, wn = (wid & 3) * 32;
    int m0 = blockIdx.y * 128, n0 = blockIdx.x * 128;
    int bb = m0 >> 10;
    float acc[4][4][4] = {};

    int chunks[2 * KTOP];
    {
        int na = 0;
        #pragma unroll
        for (int h = 0; h < H_; h++)
            if (g_mask[bb * H_ + h] != 0.f) { chunks[na++] = 2 * h; chunks[na++] = 2 * h + 1; }
    }

    int arow = tid >> 1, acol = (tid & 1) * 16;
    int brow = tid >> 3, bcol = (tid & 7) * 16;
    const bf16* Abase = g_xc + (size_t)(m0 + arow) * HID + acol;

    #define OUT_LOAD(KT, BUF)                                                        \
        {                                                                            \
            const bf16* Ag = Abase + (KT) * 32;                                      \
            CP16(sptr(&As[BUF][arow][acol]), Ag);                                    \
            CP16(sptr(&As[BUF][arow][acol + 8]), Ag + 8);                            \
            const bf16* Bg = g_wo + (size_t)((KT) * 32 + brow) * HID + n0 + bcol;    \
            CP16(sptr(&Bs[BUF][brow][bcol]), Bg);                                    \
            CP16(sptr(&Bs[BUF][brow][bcol + 8]), Bg + 8);                            \
        }

    OUT_LOAD(chunks[0], 0) CPCOMMIT();
    for (int it = 0; it < 2 * KTOP; it++) {
        int cur = it & 1;
        if (it < 2 * KTOP - 1) { OUT_LOAD(chunks[it + 1], cur ^ 1) CPCOMMIT(); CPWAIT1(); }
        else CPWAIT0();
        __syncthreads();
        #pragma unroll
        for (int kk = 0; kk < 2; kk++) {
            u32 a[4][4], bfr[2][4];
            #pragma unroll
            for (int mi = 0; mi < 4; mi++) {
                int r = wm + mi * 16 + (lane & 7) + ((lane >> 3) & 1) * 8;
                int c = kk * 16 + (lane >> 4) * 8;
                ldsm4(a[mi], sptr(&As[cur][r][c]));
            }
            #pragma unroll
            for (int nj = 0; nj < 2; nj++) {
                int rk = kk * 16 + (lane & 7) + ((lane >> 3) & 1) * 8;
                int cn = wn + nj * 16 + (lane >> 4) * 8;
                ldsm4t(bfr[nj], sptr(&Bs[cur][rk][cn]));
            }
            #pragma unroll
            for (int mi = 0; mi < 4; mi++)
                #pragma unroll
                for (int jn = 0; jn < 4; jn++)
                    mma16816(acc[mi][jn], a[mi], bfr[jn >> 1][(jn & 1) * 2], bfr[jn >> 1][(jn & 1) * 2 + 1]);
        }
        __syncthreads();
    }
    #pragma unroll
    for (int mi = 0; mi < 4; mi++) {
        int r0 = m0 + wm + mi * 16 + (lane >> 2);
        #pragma unroll
        for (int jn = 0; jn < 4; jn++) {
            int col = n0 + wn + jn * 8 + (lane & 3) * 2;
            size_t off0 = (size_t)r0 * HID + col;
            size_t off1 = off0 + 8 * HID;
            float2 x0 = *(const float2*)&X[off0];
            float2 x1 = *(const float2*)&X[off1];
            float b0f = bo[col], b1f = bo[col + 1];
            float2 o0 = { acc[mi][jn][0] + b0f + x0.x, acc[mi][jn][1] + b1f + x0.y };
            float2 o1 = { acc[mi][jn][2] + b0f + x1.x, acc[mi][jn][3] + b1f + x1.y };
            *(float2*)&g_x[off0] = o0;
            *(float2*)&g_x[off1] = o1;
        }
    }
}

// ---------------- LayerNorm (fp32, float4) ----------------
__global__ void ln_kernel(const float* __restrict__ gam, const float* __restrict__ bet,
                          float* __restrict__ out) {
    __shared__ float red[256];
    int row = blockIdx.x;
    int tid = threadIdx.x;
    const float* xr = g_x + (size_t)row * HID;
    float4 v = make_float4(0.f, 0.f, 0.f, 0.f);
    if (tid < 192) v = *(const float4*)(xr + tid * 4);
    red[tid] = v.x + v.y + v.z + v.w;
    __syncthreads();
    #pragma unroll
    for (int o = 128; o > 0; o >>= 1) {
        if (tid < o) red[tid] += red[tid + o];
        __syncthreads();
    }
    float mu = red[0] * (1.0f / HID);
    __syncthreads();
    float d0 = v.x - mu, d1 = v.y - mu, d2 = v.z - mu, d3 = v.w - mu;
    red[tid] = (tid < 192) ? (d0 * d0 + d1 * d1 + d2 * d2 + d3 * d3) : 0.f;
    __syncthreads();
    #pragma unroll
    for (int o = 128; o > 0; o >>= 1) {
        if (tid < o) red[tid] += red[tid + o];
        __syncthreads();
    }
    float inv = rsqrtf(red[0] * (1.0f / HID) + 1e-12f);
    if (tid < 192) {
        float4 g4 = *(const float4*)(gam + tid * 4);
        float4 b4 = *(const float4*)(bet + tid * 4);
        float4 o4;
        o4.x = d0 * inv * g4.x + b4.x;
        o4.y = d1 * inv * g4.y + b4.y;
        o4.z = d2 * inv * g4.z + b4.z;
        o4.w = d3 * inv * g4.w + b4.w;
        *(float4*)(out + (size_t)row * HID + tid * 4) = o4;
    }
}

// ---------------- launch ----------------
extern "C" void kernel_launch(void* const* d_in, const int* in_sizes, int n_in,
                              void* d_out, int out_size) {
    const float* X  = (const float*)d_in[0];
    const float* Wq = (const float*)d_in[1];
    const float* bq = (const float*)d_in[2];
    const float* Wk = (const float*)d_in[3];
    const float* bk = (const float*)d_in[4];
    const float* Wv = (const float*)d_in[5];
    const float* bv = (const float*)d_in[6];
    const float* Wr = (const float*)d_in[7];
    const float* br = (const float*)d_in[8];
    const float* Wo = (const float*)d_in[9];
    const float* bo = (const float*)d_in[10];
    const float* lg = (const float*)d_in[11];
    const float* lb = (const float*)d_in[12];
    float* out = (float*)d_out;

    cudaFuncSetAttribute(flash_kernel, cudaFuncAttributeMaxDynamicSharedMemorySize, FLASH_SMEM);
    cudaFuncSetAttribute(qkv_gemm, cudaFuncAttributeMaxDynamicSharedMemorySize, Q8_SMEM);

    prep_kernel<<<dim3(24, 32, 5), 256>>>(X, Wq, Wk, Wv, Wo);
    router_kernel<<<B_, 256>>>(Wr, br);

    qkv_gemm<<<dim3(H_, NROWS / 128), 256, Q8_SMEM>>>(bq, bk, bv);
    flash_kernel<<<dim3(S_ / 64, NZ), 128, FLASH_SMEM>>>();
    out_gemm<<<dim3(HID / 128, NROWS / 128), 256>>>(X, bo);
    ln_kernel<<<NROWS, 256>>>(lg, lb, out);
}

// round 17
// speedup vs baseline: 1.1124x; 1.1124x over previous
#include <cuda_runtime.h>
#include <cuda_bf16.h>
#include <cuda_fp8.h>
#include <math.h>

#define B_   8
#define S_   1024
#define H_   12
#define D_   64
#define HID  768
#define KTOP 6
#define NROWS (B_ * S_)        // 8192
#define NZ    (B_ * H_)        // 96
#define NW   (HID * HID)       // 589824

typedef unsigned int u32;
typedef unsigned char u8;
typedef __nv_bfloat16 bf16;

// ---------------- scratch ----------------
__device__ float g_rpart[B_ * 32 * HID];
__device__ float g_mask[NZ];
__device__ u8    g_x8[NROWS * HID];                // X in fp8 e4m3
__device__ u8    g_w8[3][NW];                      // Wq^T,Wk^T,Wv^T fp8 [n][k], scaled x16
__device__ bf16  g_wo[NW];                         // Wo bf16 [k][n]
__device__ bf16  g_q[NZ * S_ * D_];                // Q pre-scaled by 0.125
__device__ bf16  g_k[NZ * S_ * D_];
__device__ bf16  g_v[NZ * S_ * D_];
__device__ bf16  g_xc[NROWS * HID];                // flat ctx bf16 (masked head cols never read)
__device__ float g_x[NROWS * HID];                 // pre-LN activations fp32

// ---------------- asm helpers ----------------
__device__ __forceinline__ u32 sptr(const void* p) {
    return (u32)__cvta_generic_to_shared(p);
}
#define CP16(d, s) asm volatile("cp.async.cg.shared.global [%0],[%1],16;\n" :: "r"(d), "l"(s))
#define CPCOMMIT() asm volatile("cp.async.commit_group;\n")
#define CPWAIT0()  asm volatile("cp.async.wait_group 0;\n")
#define CPWAIT1()  asm volatile("cp.async.wait_group 1;\n")
#define CPWAIT2()  asm volatile("cp.async.wait_group 2;\n")

__device__ __forceinline__ void ldsm4(u32 (&r)[4], u32 a) {
    asm volatile("ldmatrix.sync.aligned.m8n8.x4.shared.b16 {%0,%1,%2,%3},[%4];"
                 : "=r"(r[0]), "=r"(r[1]), "=r"(r[2]), "=r"(r[3]) : "r"(a));
}
__device__ __forceinline__ void ldsm4t(u32 (&r)[4], u32 a) {
    asm volatile("ldmatrix.sync.aligned.m8n8.x4.trans.shared.b16 {%0,%1,%2,%3},[%4];"
                 : "=r"(r[0]), "=r"(r[1]), "=r"(r[2]), "=r"(r[3]) : "r"(a));
}
__device__ __forceinline__ void mma16816(float (&d)[4], const u32 (&a)[4], u32 b0, u32 b1) {
    asm volatile(
        "mma.sync.aligned.m16n8k16.row.col.f32.bf16.bf16.f32 "
        "{%0,%1,%2,%3},{%4,%5,%6,%7},{%8,%9},{%0,%1,%2,%3};"
        : "+f"(d[0]), "+f"(d[1]), "+f"(d[2]), "+f"(d[3])
        : "r"(a[0]), "r"(a[1]), "r"(a[2]), "r"(a[3]), "r"(b0), "r"(b1));
}
__device__ __forceinline__ void mma16832f8(float (&d)[4], const u32 (&a)[4], u32 b0, u32 b1) {
    asm volatile(
        "mma.sync.aligned.m16n8k32.row.col.f32.e4m3.e4m3.f32 "
        "{%0,%1,%2,%3},{%4,%5,%6,%7},{%8,%9},{%0,%1,%2,%3};"
        : "+f"(d[0]), "+f"(d[1]), "+f"(d[2]), "+f"(d[3])
        : "r"(a[0]), "r"(a[1]), "r"(a[2]), "r"(a[3]), "r"(b0), "r"(b1));
}
__device__ __forceinline__ u32 pkbf(float x, float y) {
    __nv_bfloat162 t = __floats2bfloat162_rn(x, y);
    return *(u32*)&t;
}
__device__ __forceinline__ u8 f2e4m3(float v) {
    return (u8)__nv_cvt_float_to_fp8(v, __NV_SATFINITE, __NV_E4M3);
}

// ---------------- prep: weight cvt (z<4) + X mean/fp8 cvt (z==4), one launch ----------------
__global__ void prep_kernel(const float* __restrict__ X,
                            const float* __restrict__ a, const float* __restrict__ b,
                            const float* __restrict__ c, const float* __restrict__ d) {
    int z = blockIdx.z;
    if (z < 4) {
        if (blockIdx.y >= 24) return;
        const float* s = (z == 0) ? a : (z == 1) ? b : (z == 2) ? c : d;
        __shared__ float t[32][33];
        int k0 = blockIdx.x * 32, nn0 = blockIdx.y * 32;
        int tr = threadIdx.x >> 5, tc = threadIdx.x & 31;
        #pragma unroll
        for (int p = 0; p < 4; p++)
            t[p * 8 + tr][tc] = s[(size_t)(k0 + p * 8 + tr) * HID + nn0 + tc];
        __syncthreads();
        if (z < 3) {
            #pragma unroll
            for (int p = 0; p < 4; p++)
                g_w8[z][(size_t)(nn0 + p * 8 + tr) * HID + k0 + tc] = f2e4m3(t[tc][p * 8 + tr] * 16.0f);
        } else {
            #pragma unroll
            for (int p = 0; p < 4; p++)
                g_wo[(size_t)(k0 + p * 8 + tr) * HID + nn0 + tc] = __float2bfloat16(t[p * 8 + tr][tc]);
        }
    } else {
        if (blockIdx.x >= 8) return;
        int bb = blockIdx.x, chunk = blockIdx.y, tid = threadIdx.x;
        size_t row0 = (size_t)bb * S_ + chunk * 32;
        const float* Xb = X + row0 * HID;
        u8* Ob = g_x8 + row0 * HID;
        #pragma unroll
        for (int j = 0; j < 3; j++) {
            int cc = tid + j * 256;
            float s = 0.f;
            #pragma unroll 8
            for (int r = 0; r < 32; r++) {
                float v = Xb[r * HID + cc];
                s += v;
                Ob[r * HID + cc] = f2e4m3(v);
            }
            g_rpart[(bb * 32 + chunk) * HID + cc] = s;
        }
    }
}

__global__ void router_kernel(const float* __restrict__ Wr, const float* __restrict__ br) {
    __shared__ float rin[HID];
    __shared__ float logits[H_];
    int b = blockIdx.x, tid = threadIdx.x;
    #pragma unroll
    for (int j = 0; j < 3; j++) {
        int c = tid + j * 256;
        float s = 0.f;
        #pragma unroll
        for (int p = 0; p < 32; p++) s += g_rpart[(b * 32 + p) * HID + c];
        rin[c] = s * (1.0f / S_);
    }
    __syncthreads();
    int warp = tid >> 5, lane = tid & 31;
    for (int h = warp; h < H_; h += 8) {
        float s = 0.f;
        for (int c = lane; c < HID; c += 32) s += rin[c] * Wr[c * H_ + h];
        #pragma unroll
        for (int o = 16; o > 0; o >>= 1) s += __shfl_xor_sync(0xffffffffu, s, o);
        if (lane == 0) logits[h] = s + br[h];
    }
    __syncthreads();
    if (tid < H_) {
        float v = logits[tid];
        int rank = 0;
        #pragma unroll
        for (int j = 0; j < H_; j++) {
            float u = logits[j];
            if (u > v || (u == v && j < tid)) rank++;
        }
        g_mask[b * H_ + tid] = (rank < KTOP) ? 1.0f : 0.0f;
    }
}

// ============ QKV fp8: merged q/k/v, 4-stage pipeline, m16n8k32 e4m3 ============
#define Q8_A_ST  10240
#define Q8_B_ST  5120
#define Q8_B_OFF (4 * Q8_A_ST)
#define Q8_SMEM  (Q8_B_OFF + 4 * 3 * Q8_B_ST)   // 102400 bytes

__global__ void __launch_bounds__(256, 1) qkv_gemm(
    const float* __restrict__ bq, const float* __restrict__ bk, const float* __restrict__ bv) {
    int head = blockIdx.x;
    int m0 = blockIdx.y * 128;
    int bb = m0 >> 10;
    if (g_mask[bb * H_ + head] == 0.f) return;

    extern __shared__ u8 qsm[];
    u32 smem_u = sptr(qsm);
    int n0 = head * D_;

    int tid = threadIdx.x, lane = tid & 31, wid = tid >> 5;
    int wm = (wid >> 1) * 32, wn = (wid & 1) * 32;
    float acc[3][2][4][4] = {};

    int arow = tid >> 1, ahalf = (tid & 1) * 32;
    int brow = tid >> 2, bq16 = (tid & 3) * 16;
    const u8* Abase = g_x8 + (size_t)(m0 + arow) * HID + ahalf;

    #define Q8_LOAD(KT, BUF)                                                        \
        {                                                                           \
            const u8* Ag = Abase + (KT) * 64;                                       \
            u32 ad = smem_u + (BUF) * Q8_A_ST + arow * 80 + ahalf;                  \
            CP16(ad, Ag); CP16(ad + 16, Ag + 16);                                   \
            size_t woff = (size_t)(n0 + brow) * HID + (KT) * 64 + bq16;             \
            u32 bd = smem_u + Q8_B_OFF + (BUF) * 3 * Q8_B_ST + brow * 80 + bq16;    \
            CP16(bd, g_w8[0] + woff);                                               \
            CP16(bd + Q8_B_ST, g_w8[1] + woff);                                     \
            CP16(bd + 2 * Q8_B_ST, g_w8[2] + woff);                                 \
        }

    Q8_LOAD(0, 0) CPCOMMIT();
    Q8_LOAD(1, 1) CPCOMMIT();
    Q8_LOAD(2, 2) CPCOMMIT();

    int ar8 = (lane & 7) + ((lane >> 3) & 1) * 8;
    int ac8 = (lane >> 4) * 8;
    int br8 = (lane & 7) + (lane >> 4) * 8;
    int bc8 = ((lane >> 3) & 1) * 8;

    for (int c = 0; c < 12; c++) {
        int cur = c & 3;
        if (c < 10) CPWAIT2(); else if (c < 11) CPWAIT1(); else CPWAIT0();
        __syncthreads();
        if (c < 9) { Q8_LOAD(c + 3, (c + 3) & 3) CPCOMMIT(); }

        u32 Abuf = smem_u + cur * Q8_A_ST;
        u32 Bbuf = smem_u + Q8_B_OFF + cur * 3 * Q8_B_ST;
        #pragma unroll
        for (int kk = 0; kk < 2; kk++) {
            u32 a[2][4];
            #pragma unroll
            for (int mi = 0; mi < 2; mi++) {
                int r = wm + mi * 16 + ar8;
                ldsm4(a[mi], Abuf + r * 80 + (kk * 16 + ac8) * 2);
            }
            #pragma unroll
            for (int z = 0; z < 3; z++) {
                u32 bfr[2][4];
                #pragma unroll
                for (int nj = 0; nj < 2; nj++) {
                    int rn = wn + nj * 16 + br8;
                    ldsm4(bfr[nj], Bbuf + z * Q8_B_ST + rn * 80 + (kk * 16 + bc8) * 2);
                }
                #pragma unroll
                for (int mi = 0; mi < 2; mi++)
                    #pragma unroll
                    for (int jn = 0; jn < 4; jn++)
                        mma16832f8(acc[z][mi][jn], a[mi],
                                   bfr[jn >> 1][(jn & 1) * 2], bfr[jn >> 1][(jn & 1) * 2 + 1]);
            }
        }
    }

    #pragma unroll
    for (int z = 0; z < 3; z++) {
        const float* bias = (z == 0) ? bq : (z == 1) ? bk : bv;
        bf16* out = (z == 0) ? g_q : (z == 1) ? g_k : g_v;
        float qscale = (z == 0) ? 0.125f : 1.0f;
        #pragma unroll
        for (int mi = 0; mi < 2; mi++) {
            int r0 = m0 + wm + mi * 16 + (lane >> 2);
            int s0 = r0 & (S_ - 1);
            #pragma unroll
            for (int jn = 0; jn < 4; jn++) {
                int co = wn + jn * 8 + (lane & 3) * 2;
                float b0f = bias[n0 + co], b1f = bias[n0 + co + 1];
                float c0 = (acc[z][mi][jn][0] * 0.0625f + b0f) * qscale;
                float c1 = (acc[z][mi][jn][1] * 0.0625f + b1f) * qscale;
                float c2 = (acc[z][mi][jn][2] * 0.0625f + b0f) * qscale;
                float c3 = (acc[z][mi][jn][3] * 0.0625f + b1f) * qscale;
                size_t base = ((size_t)(bb * H_ + head) * S_ + s0) * D_ + co;
                *(__nv_bfloat162*)&out[base] = __floats2bfloat162_rn(c0, c1);
                *(__nv_bfloat162*)&out[base + 8 * D_] = __floats2bfloat162_rn(c2, c3);
            }
        }
    }
}

// ============ Flash attention (R15 config): BM=128, 256 threads ============
// smem rows of [72] bf16: Q rows 0-127, K bufs at 128+cur*128, V at 384+cur*128
#define FLASH_SMEM (640 * 72 * 2)

__global__ void __launch_bounds__(256, 1) flash_kernel() {
    extern __shared__ bf16 fsm[];
    bf16 (*SM)[72] = (bf16(*)[72])fsm;
    int z = blockIdx.y;
    if (g_mask[z] == 0.f) return;      // out_gemm skips these head-chunks entirely
    int m0 = blockIdx.x * 128;
    int bb = z / H_, h = z % H_;
    int tid = threadIdx.x, lane = tid & 31, wid = tid >> 5;

    const bf16* Qg = g_q + ((size_t)z << 16);
    const bf16* Kg = g_k + ((size_t)z << 16);
    const bf16* Vg = g_v + ((size_t)z << 16);

    int arow = tid >> 1, acol = (tid & 1) << 5;

    #define LD_ROW128(DST, GP)                                        \
        {                                                             \
            u32 d = sptr(&SM[(DST) + arow][acol]);                    \
            const bf16* s = (GP) + (size_t)arow * D_ + acol;          \
            CP16(d, s); CP16(d + 16, s + 8);                          \
            CP16(d + 32, s + 16); CP16(d + 48, s + 24);               \
        }

    LD_ROW128(0, Qg + (size_t)m0 * D_)
    LD_ROW128(128, Kg)
    LD_ROW128(384, Vg)
    CPCOMMIT();
    LD_ROW128(256, Kg + (size_t)128 * D_)
    LD_ROW128(512, Vg + (size_t)128 * D_)
    CPCOMMIT();
    CPWAIT1();
    __syncthreads();

    u32 qa[4][4];
    {
        int qr = wid * 16 + (lane & 7) + ((lane >> 3) & 1) * 8;
        int qc = (lane >> 4) * 8;
        #pragma unroll
        for (int kc = 0; kc < 4; kc++)
            ldsm4(qa[kc], sptr(&SM[qr][kc * 16 + qc]));
    }

    float mrow0 = -1e30f, mrow1 = -1e30f;
    float lsum0 = 0.f, lsum1 = 0.f;
    float oacc[8][4] = {};

    for (int kt = 0; kt < 8; kt++) {
        int cur = kt & 1;
        int kbase = 128 + cur * 128;
        int vbase = 384 + cur * 128;

        float sacc[16][4] = {};
        {
            int rn8 = (lane & 7) + (lane >> 4) * 8;
            int ck8 = ((lane >> 3) & 1) * 8;
            #pragma unroll
            for (int nc = 0; nc < 8; nc++) {
                #pragma unroll
                for (int kc = 0; kc < 4; kc++) {
                    u32 kb[4];
                    ldsm4(kb, sptr(&SM[kbase + nc * 16 + rn8][kc * 16 + ck8]));
                    mma16816(sacc[nc * 2],     qa[kc], kb[0], kb[1]);
                    mma16816(sacc[nc * 2 + 1], qa[kc], kb[2], kb[3]);
                }
            }
        }

        float ml0 = mrow0, ml1 = mrow1;
        #pragma unroll
        for (int nj = 0; nj < 16; nj++) {
            ml0 = fmaxf(ml0, fmaxf(sacc[nj][0], sacc[nj][1]));
            ml1 = fmaxf(ml1, fmaxf(sacc[nj][2], sacc[nj][3]));
        }
        ml0 = fmaxf(ml0, __shfl_xor_sync(0xffffffffu, ml0, 1));
        ml0 = fmaxf(ml0, __shfl_xor_sync(0xffffffffu, ml0, 2));
        ml1 = fmaxf(ml1, __shfl_xor_sync(0xffffffffu, ml1, 1));
        ml1 = fmaxf(ml1, __shfl_xor_sync(0xffffffffu, ml1, 2));
        float al0 = __expf(mrow0 - ml0), al1 = __expf(mrow1 - ml1);
        mrow0 = ml0; mrow1 = ml1;
        lsum0 *= al0; lsum1 *= al1;

        u32 pb[16][2];
        #pragma unroll
        for (int nj = 0; nj < 16; nj++) {
            float p0 = __expf(sacc[nj][0] - ml0), p1 = __expf(sacc[nj][1] - ml0);
            float p2 = __expf(sacc[nj][2] - ml1), p3 = __expf(sacc[nj][3] - ml1);
            lsum0 += p0 + p1; lsum1 += p2 + p3;
            pb[nj][0] = pkbf(p0, p1);
            pb[nj][1] = pkbf(p2, p3);
        }
        #pragma unroll
        for (int nj = 0; nj < 8; nj++) {
            oacc[nj][0] *= al0; oacc[nj][1] *= al0;
            oacc[nj][2] *= al1; oacc[nj][3] *= al1;
        }

        {
            int vr8 = (lane & 7) + ((lane >> 3) & 1) * 8;
            int vc8 = (lane >> 4) * 8;
            #pragma unroll
            for (int pc = 0; pc < 8; pc++) {
                u32 pa[4] = {pb[pc * 2][0], pb[pc * 2][1], pb[pc * 2 + 1][0], pb[pc * 2 + 1][1]};
                #pragma unroll
                for (int vc = 0; vc < 4; vc++) {
                    u32 vb[4];
                    ldsm4t(vb, sptr(&SM[vbase + pc * 16 + vr8][vc * 16 + vc8]));
                    mma16816(oacc[vc * 2],     pa, vb[0], vb[1]);
                    mma16816(oacc[vc * 2 + 1], pa, vb[2], vb[3]);
                }
            }
        }

        __syncthreads();
        if (kt < 6) {
            int nb = kt + 2;
            LD_ROW128(128 + cur * 128, Kg + (size_t)(nb * 128) * D_)
            LD_ROW128(384 + cur * 128, Vg + (size_t)(nb * 128) * D_)
            CPCOMMIT();
            CPWAIT1();
            __syncthreads();
        } else if (kt == 6) {
            CPWAIT0();
            __syncthreads();
        }
    }

    lsum0 += __shfl_xor_sync(0xffffffffu, lsum0, 1);
    lsum0 += __shfl_xor_sync(0xffffffffu, lsum0, 2);
    lsum1 += __shfl_xor_sync(0xffffffffu, lsum1, 1);
    lsum1 += __shfl_xor_sync(0xffffffffu, lsum1, 2);
    float inv0 = 1.0f / lsum0, inv1 = 1.0f / lsum1;
    int r0 = m0 + wid * 16 + (lane >> 2);
    #pragma unroll
    for (int nj = 0; nj < 8; nj++) {
        int col = nj * 8 + (lane & 3) * 2;
        size_t b0 = (size_t)(bb * S_ + r0) * HID + h * D_ + col;
        *(__nv_bfloat162*)&g_xc[b0] = __floats2bfloat162_rn(oacc[nj][0] * inv0, oacc[nj][1] * inv0);
        *(__nv_bfloat162*)&g_xc[b0 + 8 * HID] = __floats2bfloat162_rn(oacc[nj][2] * inv1, oacc[nj][3] * inv1);
    }
}

// ============ x = ctx @ Wo + bo + residual; skip masked-head K-chunks ============
__global__ void __launch_bounds__(256, 2) out_gemm(
    const float* __restrict__ X, const float* __restrict__ bo) {
    __shared__ bf16 As[2][128][56];
    __shared__ bf16 Bs[2][32][136];
    int tid = threadIdx.x, lane = tid & 31, wid = tid >> 5;
    int wm = (wid >> 2) * 64, wn = (wid & 3) * 32;
    int m0 = blockIdx.y * 128, n0 = blockIdx.x * 128;
    int bb = m0 >> 10;
    float acc[4][4][4] = {};

    int chunks[2 * KTOP];
    {
        int na = 0;
        #pragma unroll
        for (int h = 0; h < H_; h++)
            if (g_mask[bb * H_ + h] != 0.f) { chunks[na++] = 2 * h; chunks[na++] = 2 * h + 1; }
    }

    int arow = tid >> 1, acol = (tid & 1) * 16;
    int brow = tid >> 3, bcol = (tid & 7) * 16;
    const bf16* Abase = g_xc + (size_t)(m0 + arow) * HID + acol;

    #define OUT_LOAD(KT, BUF)                                                        \
        {                                                                            \
            const bf16* Ag = Abase + (KT) * 32;                                      \
            CP16(sptr(&As[BUF][arow][acol]), Ag);                                    \
            CP16(sptr(&As[BUF][arow][acol + 8]), Ag + 8);                            \
            const bf16* Bg = g_wo + (size_t)((KT) * 32 + brow) * HID + n0 + bcol;    \
            CP16(sptr(&Bs[BUF][brow][bcol]), Bg);                                    \
            CP16(sptr(&Bs[BUF][brow][bcol + 8]), Bg + 8);                            \
        }

    OUT_LOAD(chunks[0], 0) CPCOMMIT();
    for (int it = 0; it < 2 * KTOP; it++) {
        int cur = it & 1;
        if (it < 2 * KTOP - 1) { OUT_LOAD(chunks[it + 1], cur ^ 1) CPCOMMIT(); CPWAIT1(); }
        else CPWAIT0();
        __syncthreads();
        #pragma unroll
        for (int kk = 0; kk < 2; kk++) {
            u32 a[4][4], bfr[2][4];
            #pragma unroll
            for (int mi = 0; mi < 4; mi++) {
                int r = wm + mi * 16 + (lane & 7) + ((lane >> 3) & 1) * 8;
                int c = kk * 16 + (lane >> 4) * 8;
                ldsm4(a[mi], sptr(&As[cur][r][c]));
            }
            #pragma unroll
            for (int nj = 0; nj < 2; nj++) {
                int rk = kk * 16 + (lane & 7) + ((lane >> 3) & 1) * 8;
                int cn = wn + nj * 16 + (lane >> 4) * 8;
                ldsm4t(bfr[nj], sptr(&Bs[cur][rk][cn]));
            }
            #pragma unroll
            for (int mi = 0; mi < 4; mi++)
                #pragma unroll
                for (int jn = 0; jn < 4; jn++)
                    mma16816(acc[mi][jn], a[mi], bfr[jn >> 1][(jn & 1) * 2], bfr[jn >> 1][(jn & 1) * 2 + 1]);
        }
        __syncthreads();
    }
    #pragma unroll
    for (int mi = 0; mi < 4; mi++) {
        int r0 = m0 + wm + mi * 16 + (lane >> 2);
        #pragma unroll
        for (int jn = 0; jn < 4; jn++) {
            int col = n0 + wn + jn * 8 + (lane & 3) * 2;
            size_t off0 = (size_t)r0 * HID + col;
            size_t off1 = off0 + 8 * HID;
            float2 x0 = *(const float2*)&X[off0];
            float2 x1 = *(const float2*)&X[off1];
            float b0f = bo[col], b1f = bo[col + 1];
            float2 o0 = { acc[mi][jn][0] + b0f + x0.x, acc[mi][jn][1] + b1f + x0.y };
            float2 o1 = { acc[mi][jn][2] + b0f + x1.x, acc[mi][jn][3] + b1f + x1.y };
            *(float2*)&g_x[off0] = o0;
            *(float2*)&g_x[off1] = o1;
        }
    }
}

// ---------------- LayerNorm (fp32, float4) ----------------
__global__ void ln_kernel(const float* __restrict__ gam, const float* __restrict__ bet,
                          float* __restrict__ out) {
    __shared__ float red[256];
    int row = blockIdx.x;
    int tid = threadIdx.x;
    const float* xr = g_x + (size_t)row * HID;
    float4 v = make_float4(0.f, 0.f, 0.f, 0.f);
    if (tid < 192) v = *(const float4*)(xr + tid * 4);
    red[tid] = v.x + v.y + v.z + v.w;
    __syncthreads();
    #pragma unroll
    for (int o = 128; o > 0; o >>= 1) {
        if (tid < o) red[tid] += red[tid + o];
        __syncthreads();
    }
    float mu = red[0] * (1.0f / HID);
    __syncthreads();
    float d0 = v.x - mu, d1 = v.y - mu, d2 = v.z - mu, d3 = v.w - mu;
    red[tid] = (tid < 192) ? (d0 * d0 + d1 * d1 + d2 * d2 + d3 * d3) : 0.f;
    __syncthreads();
    #pragma unroll
    for (int o = 128; o > 0; o >>= 1) {
        if (tid < o) red[tid] += red[tid + o];
        __syncthreads();
    }
    float inv = rsqrtf(red[0] * (1.0f / HID) + 1e-12f);
    if (tid < 192) {
        float4 g4 = *(const float4*)(gam + tid * 4);
        float4 b4 = *(const float4*)(bet + tid * 4);
        float4 o4;
        o4.x = d0 * inv * g4.x + b4.x;
        o4.y = d1 * inv * g4.y + b4.y;
        o4.z = d2 * inv * g4.z + b4.z;
        o4.w = d3 * inv * g4.w + b4.w;
        *(float4*)(out + (size_t)row * HID + tid * 4) = o4;
    }
}

// ---------------- launch ----------------
extern "C" void kernel_launch(void* const* d_in, const int* in_sizes, int n_in,
                              void* d_out, int out_size) {
    const float* X  = (const float*)d_in[0];
    const float* Wq = (const float*)d_in[1];
    const float* bq = (const float*)d_in[2];
    const float* Wk = (const float*)d_in[3];
    const float* bk = (const float*)d_in[4];
    const float* Wv = (const float*)d_in[5];
    const float* bv = (const float*)d_in[6];
    const float* Wr = (const float*)d_in[7];
    const float* br = (const float*)d_in[8];
    const float* Wo = (const float*)d_in[9];
    const float* bo = (const float*)d_in[10];
    const float* lg = (const float*)d_in[11];
    const float* lb = (const float*)d_in[12];
    float* out = (float*)d_out;

    cudaFuncSetAttribute(flash_kernel, cudaFuncAttributeMaxDynamicSharedMemorySize, FLASH_SMEM);
    cudaFuncSetAttribute(qkv_gemm, cudaFuncAttributeMaxDynamicSharedMemorySize, Q8_SMEM);

    prep_kernel<<<dim3(24, 32, 5), 256>>>(X, Wq, Wk, Wv, Wo);
    router_kernel<<<B_, 256>>>(Wr, br);

    qkv_gemm<<<dim3(H_, NROWS / 128), 256, Q8_SMEM>>>(bq, bk, bv);
    flash_kernel<<<dim3(S_ / 128, NZ), 256, FLASH_SMEM>>>();
    out_gemm<<<dim3(HID / 128, NROWS / 128), 256>>>(X, bo);
    ln_kernel<<<NROWS, 256>>>(lg, lb, out);
}